// round 14
// baseline (speedup 1.0000x reference)
#include <cuda_runtime.h>
#include <math.h>

#define NN 100000
#define NE 1600000

// ---------------- static scratch (no allocations allowed) ----------------
__device__ int   g_row[NE];
__device__ int   g_col[NE];
__device__ int   g_cnt[NN];
__device__ int   g_ptr[NN + 1];
__device__ int   g_fill[NN];
__device__ int   g_src[NE];
__device__ int   g_csum[256];
__device__ int   g_is64;
__device__ __align__(16) float g_enorm[NE];
__device__ __align__(16) float g_dis[NN];
__device__ __align__(16) float g_z[(size_t)NN * 512];    // stacked z_k
__device__ __align__(16) float g_sa[(size_t)NN * 128];
__device__ __align__(16) float g_sb[(size_t)NN * 128];

// internal buffer IDs: 0=g_z 1=g_sa 2=g_sb
__device__ __forceinline__ float* devbuf(int id) {
    switch (id) {
        case 0: return g_z;
        case 1: return g_sa;
        default: return g_sb;
    }
}

// ---------------- JAX threefry2x32 (partitionable convention, CONFIRMED) ------------
__host__ __device__ __forceinline__ unsigned rotl32(unsigned x, int r) {
    return (x << r) | (x >> (32 - r));
}

__host__ __device__ inline void threefry2x32(unsigned k0, unsigned k1,
                                             unsigned x0, unsigned x1,
                                             unsigned& o0, unsigned& o1) {
    unsigned ks0 = k0, ks1 = k1, ks2 = k0 ^ k1 ^ 0x1BD11BDAu;
    x0 += ks0; x1 += ks1;
#define TF_R(r) { x0 += x1; x1 = rotl32(x1, (r)); x1 ^= x0; }
    TF_R(13) TF_R(15) TF_R(26) TF_R(6)   x0 += ks1; x1 += ks2 + 1u;
    TF_R(17) TF_R(29) TF_R(16) TF_R(24)  x0 += ks2; x1 += ks0 + 2u;
    TF_R(13) TF_R(15) TF_R(26) TF_R(6)   x0 += ks0; x1 += ks1 + 3u;
    TF_R(17) TF_R(29) TF_R(16) TF_R(24)  x0 += ks1; x1 += ks2 + 4u;
    TF_R(13) TF_R(15) TF_R(26) TF_R(6)   x0 += ks2; x1 += ks0 + 5u;
#undef TF_R
    o0 = x0; o1 = x1;
}

__device__ __forceinline__ float drop_apply(float v, int i, unsigned k0, unsigned k1) {
    unsigned o0, o1;
    threefry2x32(k0, k1, 0u, (unsigned)i, o0, o1);
    unsigned bits = o0 ^ o1;
    return (bits & 0x80000000u) ? 0.f : 2.0f * v;
}

// ---------------- f32x2 helpers ----------------
__device__ __forceinline__ unsigned long long dup2(float b) {
    unsigned long long r;
    asm("mov.b64 %0, {%1, %1};" : "=l"(r) : "f"(b));
    return r;
}
__device__ __forceinline__ void fma2(unsigned long long& acc, unsigned long long a,
                                     unsigned long long b) {
    asm("fma.rn.f32x2 %0, %1, %2, %0;" : "+l"(acc) : "l"(a), "l"(b));
}
__device__ __forceinline__ void unpack2(unsigned long long v, float& lo, float& hi) {
    asm("mov.b64 {%0, %1}, %2;" : "=f"(lo), "=f"(hi) : "l"(v));
}

// ---------------- graph prep ----------------
__global__ void zero_cnt_kernel() {
    int i = blockIdx.x * blockDim.x + threadIdx.x;
    if (i < NN) g_cnt[i] = 0;
}

__global__ void detect_kernel(const int* ei32) {
    if (blockIdx.x == 0 && threadIdx.x == 0) {
        int zeros = 0;
        for (int i = 1; i < 64; i += 2) zeros += (ei32[i] == 0);
        g_is64 = (zeros == 32) ? 1 : 0;
    }
}

__global__ void prep_edges(const void* eiv) {
    int e = blockIdx.x * blockDim.x + threadIdx.x;
    if (e >= NE) return;
    int r, c;
    if (g_is64) {
        const long long* ei = (const long long*)eiv;
        r = (int)ei[e];
        c = (int)ei[NE + e];
    } else {
        const int* ei = (const int*)eiv;
        r = ei[e];
        c = ei[NE + e];
    }
    if ((unsigned)r < NN && (unsigned)c < NN) {
        g_row[e] = r;
        g_col[e] = c;
        atomicAdd(&g_cnt[c], 1);
    } else {
        g_row[e] = -1;
        g_col[e] = 0;
    }
}

// 3-kernel hierarchical scan (global memory; phase-A measured 37us in R12)
__global__ void scanA_kernel() {
    int t = blockIdx.x * blockDim.x + threadIdx.x;
    if (t >= 250) return;
    int base = t * 400;
    int s = 0;
    for (int i = 0; i < 400; i++) s += g_cnt[base + i];
    g_csum[t] = s;
}

__global__ void scanB_kernel() {
    if (blockIdx.x == 0 && threadIdx.x == 0) {
        int run = 0;
        for (int i = 0; i < 250; i++) {
            int v = g_csum[i];
            g_csum[i] = run;
            run += v;
        }
        g_ptr[NN] = run;
    }
}

__global__ void scanC_kernel() {
    int t = blockIdx.x * blockDim.x + threadIdx.x;
    if (t >= 250) return;
    int base = t * 400;
    int run = g_csum[t];
    for (int i = 0; i < 400; i++) {
        g_ptr[base + i] = run;
        run += g_cnt[base + i];
    }
}

__global__ void dis_fill_kernel() {
    int i = blockIdx.x * blockDim.x + threadIdx.x;
    if (i >= NN) return;
    int c = g_cnt[i];
    g_dis[i] = (c > 0) ? (1.0f / sqrtf((float)c)) : 0.0f;
    g_fill[i] = g_ptr[i];
}

__global__ void fill_csr_kernel() {
    int e = blockIdx.x * blockDim.x + threadIdx.x;
    if (e >= NE) return;
    int r = g_row[e];
    if (r < 0) return;
    int c = g_col[e];
    int p = atomicAdd(&g_fill[c], 1);
    g_src[p] = r;
    g_enorm[p] = g_dis[r] * g_dis[c];
}

// ---------------- GEMM: z[n, cb:cb+64] = X[n, :] @ Wstk^T  (+bias cols<blim) --------
// BM=128, BN=64, BK=16, 256 threads, TP=2 M-pairs x 8 cols per thread.
// B pre-duplicated into u64 pairs in smem -> inner loop: 5 LDS.128 + 16 FFMA2.
template <int KD>
__global__ void gemm_f32x2(const float* X_ext, int X_id,
                           const float* __restrict__ W,
                           const float* __restrict__ bias, int blim,
                           int ntot, float* out_ext, int out_id) {
    constexpr int BM = 128;
    constexpr int BN = 64;
    constexpr int BK = 16;

    __shared__ __align__(16) float As[BK][BM];                    // 8 KB
    __shared__ __align__(16) unsigned long long Bs2[BK][BN];      // 8 KB (dup pairs)

    const float* X = X_ext ? X_ext : devbuf(X_id);
    float* out = out_ext ? out_ext : devbuf(out_id);

    const int tid = threadIdx.x;                 // 0..255
    const int m0 = (tid & 31) * 4;               // 4 rows = 2 pairs
    const int n0 = (tid >> 5) * 8;               // 8 cols
    const int mb = blockIdx.x * BM;
    const int cb = blockIdx.y * BN;

    unsigned long long acc[2][8];
#pragma unroll
    for (int i = 0; i < 2; i++)
#pragma unroll
        for (int j = 0; j < 8; j++) acc[i][j] = 0ull;

    for (int kc = 0; kc < KD; kc += BK) {
        // As[d][m] = X[mb+m][kc+d]  (transposed store)
#pragma unroll
        for (int it = 0; it < 2; it++) {
            int idx = tid + it * 256;            // 0..511
            int dq = idx & 3, nl = idx >> 2;     // nl 0..127
            int node = mb + nl;
            float4 v = make_float4(0.f, 0.f, 0.f, 0.f);
            if (node < NN) v = *reinterpret_cast<const float4*>(&X[(size_t)node * KD + kc + dq * 4]);
            As[dq * 4 + 0][nl] = v.x;
            As[dq * 4 + 1][nl] = v.y;
            As[dq * 4 + 2][nl] = v.z;
            As[dq * 4 + 3][nl] = v.w;
        }
        // Bs2[d][o] = dup(W[cb+o][kc+d])
        {
            int dq = tid & 3, ol = tid >> 2;     // ol 0..63
            float4 v = *reinterpret_cast<const float4*>(&W[(size_t)(cb + ol) * KD + kc + dq * 4]);
            Bs2[dq * 4 + 0][ol] = dup2(v.x);
            Bs2[dq * 4 + 1][ol] = dup2(v.y);
            Bs2[dq * 4 + 2][ol] = dup2(v.z);
            Bs2[dq * 4 + 3][ol] = dup2(v.w);
        }
        __syncthreads();

#pragma unroll
        for (int d = 0; d < BK; d++) {
            ulonglong2 ap = *reinterpret_cast<const ulonglong2*>(&As[d][m0]);
            ulonglong2 b01 = *reinterpret_cast<const ulonglong2*>(&Bs2[d][n0]);
            ulonglong2 b23 = *reinterpret_cast<const ulonglong2*>(&Bs2[d][n0 + 2]);
            ulonglong2 b45 = *reinterpret_cast<const ulonglong2*>(&Bs2[d][n0 + 4]);
            ulonglong2 b67 = *reinterpret_cast<const ulonglong2*>(&Bs2[d][n0 + 6]);
            fma2(acc[0][0], ap.x, b01.x); fma2(acc[1][0], ap.y, b01.x);
            fma2(acc[0][1], ap.x, b01.y); fma2(acc[1][1], ap.y, b01.y);
            fma2(acc[0][2], ap.x, b23.x); fma2(acc[1][2], ap.y, b23.x);
            fma2(acc[0][3], ap.x, b23.y); fma2(acc[1][3], ap.y, b23.y);
            fma2(acc[0][4], ap.x, b45.x); fma2(acc[1][4], ap.y, b45.x);
            fma2(acc[0][5], ap.x, b45.y); fma2(acc[1][5], ap.y, b45.y);
            fma2(acc[0][6], ap.x, b67.x); fma2(acc[1][6], ap.y, b67.x);
            fma2(acc[0][7], ap.x, b67.y); fma2(acc[1][7], ap.y, b67.y);
        }
        __syncthreads();
    }

    float bvals[8];
#pragma unroll
    for (int j = 0; j < 8; j++) {
        int gcol = cb + n0 + j;
        bvals[j] = (bias && gcol < blim) ? bias[gcol] : 0.f;
    }

#pragma unroll
    for (int i = 0; i < 2; i++) {
        float lo[8], hi[8];
#pragma unroll
        for (int j = 0; j < 8; j++) unpack2(acc[i][j], lo[j], hi[j]);
        int row0 = mb + m0 + 2 * i;
        if (row0 < NN) {
            float* po = out + (size_t)row0 * ntot + cb + n0;
            *reinterpret_cast<float4*>(po) =
                make_float4(lo[0] + bvals[0], lo[1] + bvals[1], lo[2] + bvals[2], lo[3] + bvals[3]);
            *reinterpret_cast<float4*>(po + 4) =
                make_float4(lo[4] + bvals[4], lo[5] + bvals[5], lo[6] + bvals[6], lo[7] + bvals[7]);
        }
        if (row0 + 1 < NN) {
            float* po = out + (size_t)(row0 + 1) * ntot + cb + n0;
            *reinterpret_cast<float4*>(po) =
                make_float4(hi[0] + bvals[0], hi[1] + bvals[1], hi[2] + bvals[2], hi[3] + bvals[3]);
            *reinterpret_cast<float4*>(po + 4) =
                make_float4(hi[4] + bvals[4], hi[5] + bvals[5], hi[6] + bvals[6], hi[7] + bvals[7]);
        }
    }
}

// ---------------- fused Horner hop: out[c] = sum_e norm*hin[src] + z[c] (+post) ------
// POST: 0 = none, 1 = dropout, 2 = elu+dropout
template <int D, int POST>
__global__ void prop_fused(const float* hin_ext, int hin_id, int hin_str, int hin_off,
                           int z_str, int z_off,
                           float* out_ext, int out_id,
                           unsigned k0, unsigned k1) {
    const float* __restrict__ hin = (hin_ext ? hin_ext : devbuf(hin_id)) + hin_off;
    const float* __restrict__ z = g_z + z_off;
    float* __restrict__ outp = out_ext ? out_ext : devbuf(out_id);
    int w = blockIdx.x * (blockDim.x >> 5) + (threadIdx.x >> 5);
    if (w >= NN) return;
    int lane = threadIdx.x & 31;
    int s = g_ptr[w], e = g_ptr[w + 1];

    if (D == 128) {
        float4 acc = make_float4(0.f, 0.f, 0.f, 0.f);
        for (int i = s; i < e; i++) {
            int r = g_src[i];
            float wt = g_enorm[i];
            float4 v = *reinterpret_cast<const float4*>(hin + (size_t)r * hin_str + lane * 4);
            acc.x += wt * v.x; acc.y += wt * v.y; acc.z += wt * v.z; acc.w += wt * v.w;
        }
        float4 zv = *reinterpret_cast<const float4*>(z + (size_t)w * z_str + lane * 4);
        acc.x += zv.x; acc.y += zv.y; acc.z += zv.z; acc.w += zv.w;
        if (POST == 1) {
            int i0 = w * 128 + lane * 4;
            acc.x = drop_apply(acc.x, i0 + 0, k0, k1);
            acc.y = drop_apply(acc.y, i0 + 1, k0, k1);
            acc.z = drop_apply(acc.z, i0 + 2, k0, k1);
            acc.w = drop_apply(acc.w, i0 + 3, k0, k1);
        }
        *reinterpret_cast<float4*>(outp + (size_t)w * 128 + lane * 4) = acc;
    } else if (D == 64) {
        float2 acc = make_float2(0.f, 0.f);
        for (int i = s; i < e; i++) {
            int r = g_src[i];
            float wt = g_enorm[i];
            float2 v = *reinterpret_cast<const float2*>(hin + (size_t)r * hin_str + lane * 2);
            acc.x += wt * v.x; acc.y += wt * v.y;
        }
        float2 zv = *reinterpret_cast<const float2*>(z + (size_t)w * z_str + lane * 2);
        acc.x += zv.x; acc.y += zv.y;
        if (POST == 2) {
            acc.x = (acc.x > 0.f) ? acc.x : expm1f(acc.x);
            acc.y = (acc.y > 0.f) ? acc.y : expm1f(acc.y);
            int i0 = w * 64 + lane * 2;
            acc.x = drop_apply(acc.x, i0 + 0, k0, k1);
            acc.y = drop_apply(acc.y, i0 + 1, k0, k1);
        }
        *reinterpret_cast<float2*>(outp + (size_t)w * 64 + lane * 2) = acc;
    } else {  // D == 16
        if (lane < 16) {
            float acc = 0.f;
            for (int i = s; i < e; i++) {
                int r = g_src[i];
                acc += g_enorm[i] * hin[(size_t)r * hin_str + lane];
            }
            acc += z[(size_t)w * z_str + lane];
            outp[(size_t)w * 16 + lane] = acc;
        }
    }
}

// ---------------- host orchestration: kernel launches ONLY ----------------
extern "C" void kernel_launch(void* const* d_in, const int* in_sizes, int n_in,
                              void* d_out, int out_size) {
    const float* x  = (const float*)d_in[0];
    const void*  ei = (const void*)d_in[1];
    const float* W1 = (const float*)d_in[2];
    const float* b1 = (const float*)d_in[3];
    const float* W2 = (const float*)d_in[4];
    const float* b2 = (const float*)d_in[5];
    const float* W3 = (const float*)d_in[6];
    const float* b3 = (const float*)d_in[7];
    float* out = (float*)d_out;

    unsigned d10, d11, d20, d21;
    threefry2x32(0u, 42u, 0u, 0u, d10, d11);
    threefry2x32(0u, 42u, 0u, 1u, d20, d21);

    const int mgrid = (NN + 127) / 128;    // 782
    const int pgrid = (NN + 7) / 8;

    // Launch order arranged so the 6th launch (ncu -s 5 -c 1) is the layer-1 GEMM.
    zero_cnt_kernel<<<(NN + 255) / 256, 256>>>();                    // 1
    detect_kernel<<<1, 32>>>((const int*)ei);                        // 2
    prep_edges<<<(NE + 255) / 256, 256>>>(ei);                       // 3
    scanA_kernel<<<1, 256>>>();                                      // 4
    scanB_kernel<<<1, 32>>>();                                       // 5
    gemm_f32x2<128><<<dim3(mgrid, 8), 256>>>(x, -1, W1, b1, 128, 512, nullptr, 0);  // 6 <- profiled
    scanC_kernel<<<1, 256>>>();                                      // 7
    dis_fill_kernel<<<(NN + 255) / 256, 256>>>();                    // 8
    fill_csr_kernel<<<(NE + 255) / 256, 256>>>();                    // 9

    // ---- layer 1 Horner props at 128d ----
    prop_fused<128, 0><<<pgrid, 256>>>(nullptr, 0, 512, 3 * 128, 512, 2 * 128, nullptr, 1, 0u, 0u); // sa = A z3 + z2
    prop_fused<128, 0><<<pgrid, 256>>>(nullptr, 1, 128, 0, 512, 128, nullptr, 2, 0u, 0u);           // sb = A sa + z1
    prop_fused<128, 1><<<pgrid, 256>>>(nullptr, 2, 128, 0, 512, 0, nullptr, 1, d10, d11);           // sa = drop(A sb + z0)

    // ---- layer 2: z = h1 @ W2stk^T [100k,256]; props at 64d ----
    gemm_f32x2<128><<<dim3(mgrid, 4), 256>>>(nullptr, 1, W2, b2, 64, 256, nullptr, 0);
    prop_fused<64, 0><<<pgrid, 256>>>(nullptr, 0, 256, 3 * 64, 256, 2 * 64, nullptr, 2, 0u, 0u);    // sb = A z3 + z2
    prop_fused<64, 0><<<pgrid, 256>>>(nullptr, 2, 64, 0, 256, 64, nullptr, 1, 0u, 0u);              // sa = A sb + z1
    prop_fused<64, 2><<<pgrid, 256>>>(nullptr, 1, 64, 0, 256, 0, nullptr, 2, d20, d21);             // sb = drop(elu(A sa + z0))

    // ---- layer 3: z = h2 @ W3stk^T [100k,64]; props at 16d ----
    gemm_f32x2<64><<<dim3(mgrid, 1), 256>>>(nullptr, 2, W3, b3, 16, 64, nullptr, 0);
    prop_fused<16, 0><<<pgrid, 256>>>(nullptr, 0, 64, 3 * 16, 64, 2 * 16, nullptr, 1, 0u, 0u);      // sa = A z3 + z2
    prop_fused<16, 0><<<pgrid, 256>>>(nullptr, 1, 16, 0, 64, 16, nullptr, 2, 0u, 0u);               // sb = A sa + z1
    prop_fused<16, 0><<<pgrid, 256>>>(nullptr, 2, 16, 0, 64, 0, out, -1, 0u, 0u);                   // out = A sb + z0
}

// round 15
// speedup vs baseline: 1.6262x; 1.6262x over previous
#include <cuda_runtime.h>
#include <math.h>

#define NN 100000
#define NE 1600000
#define NBLK 391   // ceil(NN/256)

// ---------------- static scratch (no allocations allowed) ----------------
__device__ int   g_row[NE];
__device__ int   g_col[NE];
__device__ int   g_cnt[NN];
__device__ int   g_ptr[NN + 1];
__device__ int   g_fill[NN];
__device__ int   g_src[NE];
__device__ int   g_csum[512];
__device__ int   g_is64;
__device__ __align__(16) float g_enorm[NE];
__device__ __align__(16) float g_dis[NN];
__device__ __align__(16) float g_ha[(size_t)NN * 128];
__device__ __align__(16) float g_hb[(size_t)NN * 128];
__device__ __align__(16) float g_o1[(size_t)NN * 128];
__device__ __align__(16) float g_o2[(size_t)NN * 64];

// internal buffer IDs: 0=g_ha 1=g_hb 2=g_o1 3=g_o2
__device__ __forceinline__ float* devbuf(int id) {
    switch (id) {
        case 0: return g_ha;
        case 1: return g_hb;
        case 2: return g_o1;
        default: return g_o2;
    }
}

// ---------------- JAX threefry2x32 (partitionable convention, CONFIRMED) ------------
__host__ __device__ __forceinline__ unsigned rotl32(unsigned x, int r) {
    return (x << r) | (x >> (32 - r));
}

__host__ __device__ inline void threefry2x32(unsigned k0, unsigned k1,
                                             unsigned x0, unsigned x1,
                                             unsigned& o0, unsigned& o1) {
    unsigned ks0 = k0, ks1 = k1, ks2 = k0 ^ k1 ^ 0x1BD11BDAu;
    x0 += ks0; x1 += ks1;
#define TF_R(r) { x0 += x1; x1 = rotl32(x1, (r)); x1 ^= x0; }
    TF_R(13) TF_R(15) TF_R(26) TF_R(6)   x0 += ks1; x1 += ks2 + 1u;
    TF_R(17) TF_R(29) TF_R(16) TF_R(24)  x0 += ks2; x1 += ks0 + 2u;
    TF_R(13) TF_R(15) TF_R(26) TF_R(6)   x0 += ks0; x1 += ks1 + 3u;
    TF_R(17) TF_R(29) TF_R(16) TF_R(24)  x0 += ks1; x1 += ks2 + 4u;
    TF_R(13) TF_R(15) TF_R(26) TF_R(6)   x0 += ks2; x1 += ks0 + 5u;
#undef TF_R
    o0 = x0; o1 = x1;
}

__device__ __forceinline__ float drop_apply(float v, int i, unsigned k0, unsigned k1) {
    unsigned o0, o1;
    threefry2x32(k0, k1, 0u, (unsigned)i, o0, o1);
    unsigned bits = o0 ^ o1;
    return (bits & 0x80000000u) ? 0.f : 2.0f * v;
}

// ---------------- graph prep ----------------
__global__ void zero_cnt_kernel() {
    int i = blockIdx.x * blockDim.x + threadIdx.x;
    if (i < NN) g_cnt[i] = 0;
}

__global__ void detect_kernel(const int* ei32) {
    if (blockIdx.x == 0 && threadIdx.x == 0) {
        int zeros = 0;
        for (int i = 1; i < 64; i += 2) zeros += (ei32[i] == 0);
        g_is64 = (zeros == 32) ? 1 : 0;
    }
}

__global__ void prep_edges(const void* eiv) {
    int e = blockIdx.x * blockDim.x + threadIdx.x;
    if (e >= NE) return;
    int r, c;
    if (g_is64) {
        const long long* ei = (const long long*)eiv;
        r = (int)ei[e];
        c = (int)ei[NE + e];
    } else {
        const int* ei = (const int*)eiv;
        r = ei[e];
        c = ei[NE + e];
    }
    if ((unsigned)r < NN && (unsigned)c < NN) {
        g_row[e] = r;
        g_col[e] = c;
        atomicAdd(&g_cnt[c], 1);
    } else {
        g_row[e] = -1;
        g_col[e] = 0;
    }
}

// ---------------- parallel 3-phase scan ----------------
__global__ void scanA_kernel() {   // per-block reduction of 256 counts
    __shared__ int ss[256];
    int t = threadIdx.x;
    int i = blockIdx.x * 256 + t;
    ss[t] = (i < NN) ? g_cnt[i] : 0;
    __syncthreads();
    for (int off = 128; off > 0; off >>= 1) {
        if (t < off) ss[t] += ss[t + off];
        __syncthreads();
    }
    if (t == 0) g_csum[blockIdx.x] = ss[0];
}

__global__ void scanB_kernel() {   // 1 block, 512 threads: scan block sums
    __shared__ int ss[512];
    int t = threadIdx.x;
    int v = (t < NBLK) ? g_csum[t] : 0;
    ss[t] = v;
    __syncthreads();
    for (int off = 1; off < 512; off <<= 1) {
        int u = (t >= off) ? ss[t - off] : 0;
        __syncthreads();
        ss[t] += u;
        __syncthreads();
    }
    if (t < NBLK) g_csum[t] = ss[t] - v;     // exclusive
    if (t == 511) g_ptr[NN] = ss[511];       // total
}

__global__ void scanC_kernel() {   // per-block exclusive scan + base
    __shared__ int ss[256];
    int t = threadIdx.x;
    int i = blockIdx.x * 256 + t;
    int c = (i < NN) ? g_cnt[i] : 0;
    ss[t] = c;
    __syncthreads();
    for (int off = 1; off < 256; off <<= 1) {
        int u = (t >= off) ? ss[t - off] : 0;
        __syncthreads();
        ss[t] += u;
        __syncthreads();
    }
    if (i < NN) g_ptr[i] = g_csum[blockIdx.x] + ss[t] - c;
}

__global__ void dis_fill_kernel() {
    int i = blockIdx.x * blockDim.x + threadIdx.x;
    if (i >= NN) return;
    int c = g_cnt[i];
    g_dis[i] = (c > 0) ? (1.0f / sqrtf((float)c)) : 0.0f;
    g_fill[i] = g_ptr[i];
}

__global__ void fill_csr_kernel() {
    int e = blockIdx.x * blockDim.x + threadIdx.x;
    if (e >= NE) return;
    int r = g_row[e];
    if (r < 0) return;
    int c = g_col[e];
    int p = atomicAdd(&g_fill[c], 1);
    g_src[p] = r;
    g_enorm[p] = g_dis[r] * g_dis[c];
}

// ---------------- propagation hop (R12-proven) ----------------
template <int D>
__global__ void prop_kernel(const float* hin_ext, int hin_id, int hout_id) {
    const float* __restrict__ hin = hin_ext ? hin_ext : devbuf(hin_id);
    float* __restrict__ hout = devbuf(hout_id);
    int w = blockIdx.x * (blockDim.x >> 5) + (threadIdx.x >> 5);
    if (w >= NN) return;
    int lane = threadIdx.x & 31;
    int s = g_ptr[w], e = g_ptr[w + 1];
    if (D == 128) {
        float4 acc = make_float4(0.f, 0.f, 0.f, 0.f);
        for (int i = s; i < e; i++) {
            int r = g_src[i];
            float wt = g_enorm[i];
            float4 v = *reinterpret_cast<const float4*>(hin + (size_t)r * 128 + lane * 4);
            acc.x += wt * v.x; acc.y += wt * v.y; acc.z += wt * v.z; acc.w += wt * v.w;
        }
        *reinterpret_cast<float4*>(hout + (size_t)w * 128 + lane * 4) = acc;
    } else {
        float2 acc = make_float2(0.f, 0.f);
        for (int i = s; i < e; i++) {
            int r = g_src[i];
            float wt = g_enorm[i];
            float2 v = *reinterpret_cast<const float2*>(hin + (size_t)r * 64 + lane * 2);
            acc.x += wt * v.x; acc.y += wt * v.y;
        }
        *reinterpret_cast<float2*>(hout + (size_t)w * 64 + lane * 2) = acc;
    }
}

// ---------------- GEMM: out[n,o] (+)= X[n,:KD] @ W[o,:KD]  (+bias / +post) ----------
// BM=128, BK=16, 256 threads (16x16), TM=8 x TN=NOUT/16 micro-tile.
// As transposed [d][m] -> inner loop is vector LDS only.
// POST: 0 none, 1 dropout, 2 elu+dropout (applied only on final ACC pass)
template <int NOUT, int KD, bool ACC, int POST>
__global__ void gemm_nt(const float* X_ext, int X_id,
                        const float* __restrict__ W, const float* __restrict__ bias,
                        float* out_ext, int out_id, unsigned k0, unsigned k1) {
    constexpr int BM = 128;
    constexpr int BK = 16;
    constexpr int TM = 8;
    constexpr int TN = NOUT / 16;

    __shared__ __align__(16) float As[BK][BM];     // 8 KB
    __shared__ __align__(16) float Ws[BK][NOUT];   // <= 8 KB

    const float* __restrict__ X = X_ext ? X_ext : devbuf(X_id);
    float* __restrict__ out = out_ext ? out_ext : devbuf(out_id);

    const int tx = threadIdx.x;       // 0..15
    const int ty = threadIdx.y;       // 0..15
    const int tid = ty * 16 + tx;
    const int mb = blockIdx.x * BM;

    float acc[TM][TN];
#pragma unroll
    for (int i = 0; i < TM; i++)
#pragma unroll
        for (int j = 0; j < TN; j++) acc[i][j] = 0.f;

    for (int kc = 0; kc < KD; kc += BK) {
        // As[d][m] = X[mb+m][kc+d]
#pragma unroll
        for (int it = 0; it < 2; it++) {
            int idx = tid + it * 256;            // 0..511
            int dq = idx & 3, nl = idx >> 2;     // nl 0..127
            int node = mb + nl;
            float4 v = make_float4(0.f, 0.f, 0.f, 0.f);
            if (node < NN) v = *reinterpret_cast<const float4*>(&X[(size_t)node * KD + kc + dq * 4]);
            As[dq * 4 + 0][nl] = v.x;
            As[dq * 4 + 1][nl] = v.y;
            As[dq * 4 + 2][nl] = v.z;
            As[dq * 4 + 3][nl] = v.w;
        }
        // Ws[d][o] = W[o][kc+d]
        for (int idx = tid; idx < NOUT * BK / 4; idx += 256) {
            int dq = idx & 3, ol = idx >> 2;     // ol 0..NOUT-1
            float4 v = *reinterpret_cast<const float4*>(&W[(size_t)ol * KD + kc + dq * 4]);
            Ws[dq * 4 + 0][ol] = v.x;
            Ws[dq * 4 + 1][ol] = v.y;
            Ws[dq * 4 + 2][ol] = v.z;
            Ws[dq * 4 + 3][ol] = v.w;
        }
        __syncthreads();

#pragma unroll
        for (int d = 0; d < BK; d++) {
            float a[TM], b[TN];
            *reinterpret_cast<float4*>(&a[0]) = *reinterpret_cast<const float4*>(&As[d][ty * TM]);
            *reinterpret_cast<float4*>(&a[4]) = *reinterpret_cast<const float4*>(&As[d][ty * TM + 4]);
            if (TN == 8) {
                *reinterpret_cast<float4*>(&b[0]) = *reinterpret_cast<const float4*>(&Ws[d][tx * TN]);
                *reinterpret_cast<float4*>(&b[4]) = *reinterpret_cast<const float4*>(&Ws[d][tx * TN + 4]);
            } else if (TN == 4) {
                *reinterpret_cast<float4*>(&b[0]) = *reinterpret_cast<const float4*>(&Ws[d][tx * TN]);
            } else {
                b[0] = Ws[d][tx];
            }
#pragma unroll
            for (int i = 0; i < TM; i++)
#pragma unroll
                for (int j = 0; j < TN; j++) acc[i][j] += a[i] * b[j];
        }
        __syncthreads();
    }

#pragma unroll
    for (int i = 0; i < TM; i++) {
        int node = mb + ty * TM + i;
        if (node >= NN) continue;
        float* po = out + (size_t)node * NOUT + tx * TN;
        float v[TN];
        if (ACC) {
            if (TN == 8) {
                *reinterpret_cast<float4*>(&v[0]) = *reinterpret_cast<const float4*>(po);
                *reinterpret_cast<float4*>(&v[4]) = *reinterpret_cast<const float4*>(po + 4);
            } else if (TN == 4) {
                *reinterpret_cast<float4*>(&v[0]) = *reinterpret_cast<const float4*>(po);
            } else {
                v[0] = po[0];
            }
#pragma unroll
            for (int j = 0; j < TN; j++) v[j] += acc[i][j];
        } else {
#pragma unroll
            for (int j = 0; j < TN; j++) v[j] = acc[i][j] + bias[tx * TN + j];
        }
        if (POST == 2) {
#pragma unroll
            for (int j = 0; j < TN; j++) v[j] = (v[j] > 0.f) ? v[j] : expm1f(v[j]);
        }
        if (POST >= 1) {
            int i0 = node * NOUT + tx * TN;
#pragma unroll
            for (int j = 0; j < TN; j++) v[j] = drop_apply(v[j], i0 + j, k0, k1);
        }
        if (TN == 8) {
            *reinterpret_cast<float4*>(po) = *reinterpret_cast<const float4*>(&v[0]);
            *reinterpret_cast<float4*>(po + 4) = *reinterpret_cast<const float4*>(&v[4]);
        } else if (TN == 4) {
            *reinterpret_cast<float4*>(po) = *reinterpret_cast<const float4*>(&v[0]);
        } else {
            po[0] = v[0];
        }
    }
}

// ---------------- host orchestration: kernel launches ONLY ----------------
extern "C" void kernel_launch(void* const* d_in, const int* in_sizes, int n_in,
                              void* d_out, int out_size) {
    const float* x  = (const float*)d_in[0];
    const void*  ei = (const void*)d_in[1];
    const float* W1 = (const float*)d_in[2];
    const float* b1 = (const float*)d_in[3];
    const float* W2 = (const float*)d_in[4];
    const float* b2 = (const float*)d_in[5];
    const float* W3 = (const float*)d_in[6];
    const float* b3 = (const float*)d_in[7];
    float* out = (float*)d_out;

    unsigned d10, d11, d20, d21;
    threefry2x32(0u, 42u, 0u, 0u, d10, d11);
    threefry2x32(0u, 42u, 0u, 1u, d20, d21);

    const int mgrid = (NN + 127) / 128;    // 782
    const int pgrid = (NN + 7) / 8;
    dim3 gb(16, 16);

    // prep (layer-1 k=0 GEMM placed 4th -> it's the launch ncu captures)
    zero_cnt_kernel<<<(NN + 255) / 256, 256>>>();                    // 1
    detect_kernel<<<1, 32>>>((const int*)ei);                        // 2
    prep_edges<<<(NE + 255) / 256, 256>>>(ei);                       // 3
    gemm_nt<128, 128, false, 0><<<mgrid, gb>>>(x, -1, W1, b1, nullptr, 2, 0u, 0u);  // 4 <- profiled
    scanA_kernel<<<NBLK, 256>>>();                                   // 5
    scanB_kernel<<<1, 512>>>();                                      // 6
    scanC_kernel<<<NBLK, 256>>>();                                   // 7
    dis_fill_kernel<<<(NN + 255) / 256, 256>>>();                    // 8
    fill_csr_kernel<<<(NE + 255) / 256, 256>>>();                    // 9

    // ---- layer 1: 128 -> 128 -> o1(id2); final GEMM fuses dropout ----
    prop_kernel<128><<<pgrid, 256>>>(x, -1, 0);                                          // ha = A x
    gemm_nt<128, 128, true, 0><<<mgrid, gb>>>(nullptr, 0, W1 + 1 * 16384, nullptr, nullptr, 2, 0u, 0u);
    prop_kernel<128><<<pgrid, 256>>>(nullptr, 0, 1);                                     // hb = A ha
    gemm_nt<128, 128, true, 0><<<mgrid, gb>>>(nullptr, 1, W1 + 2 * 16384, nullptr, nullptr, 2, 0u, 0u);
    prop_kernel<128><<<pgrid, 256>>>(nullptr, 1, 0);                                     // ha = A hb
    gemm_nt<128, 128, true, 1><<<mgrid, gb>>>(nullptr, 0, W1 + 3 * 16384, nullptr, nullptr, 2, d10, d11);

    // ---- layer 2: 128 -> 64 -> o2(id3); final GEMM fuses elu+dropout ----
    gemm_nt<64, 128, false, 0><<<mgrid, gb>>>(nullptr, 2, W2, b2, nullptr, 3, 0u, 0u);
    prop_kernel<128><<<pgrid, 256>>>(nullptr, 2, 0);                                     // ha = A o1
    gemm_nt<64, 128, true, 0><<<mgrid, gb>>>(nullptr, 0, W2 + 1 * 8192, nullptr, nullptr, 3, 0u, 0u);
    prop_kernel<128><<<pgrid, 256>>>(nullptr, 0, 1);                                     // hb = A ha
    gemm_nt<64, 128, true, 0><<<mgrid, gb>>>(nullptr, 1, W2 + 2 * 8192, nullptr, nullptr, 3, 0u, 0u);
    prop_kernel<128><<<pgrid, 256>>>(nullptr, 1, 0);                                     // ha = A hb
    gemm_nt<64, 128, true, 2><<<mgrid, gb>>>(nullptr, 0, W2 + 3 * 8192, nullptr, nullptr, 3, d20, d21);

    // ---- layer 3: 64 -> 16 -> out (external) ----
    gemm_nt<16, 64, false, 0><<<mgrid, gb>>>(nullptr, 3, W3, b3, out, -1, 0u, 0u);
    prop_kernel<64><<<pgrid, 256>>>(nullptr, 3, 0);                                      // ha = A o2 (64d)
    gemm_nt<16, 64, true, 0><<<mgrid, gb>>>(nullptr, 0, W3 + 1 * 1024, nullptr, out, -1, 0u, 0u);
    prop_kernel<64><<<pgrid, 256>>>(nullptr, 0, 1);                                      // hb = A ha
    gemm_nt<16, 64, true, 0><<<mgrid, gb>>>(nullptr, 1, W3 + 2 * 1024, nullptr, out, -1, 0u, 0u);
    prop_kernel<64><<<pgrid, 256>>>(nullptr, 1, 0);                                      // ha = A hb
    gemm_nt<16, 64, true, 0><<<mgrid, gb>>>(nullptr, 0, W3 + 3 * 1024, nullptr, out, -1, 0u, 0u);
}